// round 1
// baseline (speedup 1.0000x reference)
#include <cuda_runtime.h>
#include <cstdint>
#include <math_constants.h>

// Problem constants
#define T_STEPS 128
#define IN_SZ   64
#define H       2048
#define OUT_SZ  4096
#define G4      (4*H)   // 8192 gate rows per layer

// ---------------- device scratch (no allocations allowed) ----------------
__device__ __align__(16) float g_A0[T_STEPS * G4];      // precomputed Wih0[:,1:]@x_t + bih0 + bhh0, [t][row]
__device__ __align__(16) float g_gum[T_STEPS * OUT_SZ]; // precomputed gumbel noise
__device__ uint32_t g_keys2[2 * T_STEPS];               // per-step threefry keys
__device__ __align__(16) float g_h0[2][H];
__device__ __align__(16) float g_h1[2][H];
__device__ __align__(16) float g_c0[H];
__device__ __align__(16) float g_c1[H];
__device__ float g_prev;
__device__ __align__(16) float g_logits[OUT_SZ];
__device__ __align__(16) float g_pert[OUT_SZ];

// ---------------- threefry2x32 (JAX-compatible) ----------------
__device__ __forceinline__ void tf2x32(uint32_t k0, uint32_t k1, uint32_t& x0, uint32_t& x1) {
    uint32_t ks2 = k0 ^ k1 ^ 0x1BD11BDAu;
    x0 += k0; x1 += k1;
#define TF_RND(r) { x0 += x1; x1 = (x1 << (r)) | (x1 >> (32 - (r))); x1 ^= x0; }
    TF_RND(13) TF_RND(15) TF_RND(26) TF_RND(6)   x0 += k1;  x1 += ks2 + 1u;
    TF_RND(17) TF_RND(29) TF_RND(16) TF_RND(24)  x0 += ks2; x1 += k0 + 2u;
    TF_RND(13) TF_RND(15) TF_RND(26) TF_RND(6)   x0 += k0;  x1 += k1 + 3u;
    TF_RND(17) TF_RND(29) TF_RND(16) TF_RND(24)  x0 += k1;  x1 += ks2 + 4u;
    TF_RND(13) TF_RND(15) TF_RND(26) TF_RND(6)   x0 += ks2; x1 += k0 + 5u;
#undef TF_RND
}

// keys[t] = threefry((0,42), hi=0, lo=t)   [jax_threefry_partitionable fold-like split]
__global__ void k_keys() {
    int t = threadIdx.x;  // 128 threads
    uint32_t x0 = 0u, x1 = (uint32_t)t;
    tf2x32(0u, 42u, x0, x1);
    g_keys2[2 * t]     = x0;
    g_keys2[2 * t + 1] = x1;
}

// gumbel[t][i]: bits = xor of threefry(key_t, hi=0, lo=i); uniform -> -log(-log(u))
__global__ void k_gumbel() {
    int idx = blockIdx.x * blockDim.x + threadIdx.x; // 0 .. 128*4096
    int t = idx >> 12;
    int i = idx & (OUT_SZ - 1);
    uint32_t x0 = 0u, x1 = (uint32_t)i;
    tf2x32(g_keys2[2 * t], g_keys2[2 * t + 1], x0, x1);
    uint32_t bits = x0 ^ x1;
    float f = __uint_as_float((bits >> 9) | 0x3f800000u) - 1.0f;
    const float TINY = 1.17549435e-38f;
    float u = fmaxf(f + TINY, TINY);
    g_gum[idx] = -logf(-logf(u));
}

__global__ void k_init(const float* __restrict__ h0in, const float* __restrict__ c0in) {
    int i = blockIdx.x * blockDim.x + threadIdx.x;
    if (i < H) {
        g_h0[0][i] = h0in[i];
        g_c0[i]    = c0in[i];
        g_h1[0][i] = h0in[H + i];
        g_c1[i]    = c0in[H + i];
    }
    if (i == 0) g_prev = 1.0f;
}

// A0[t][r] = bih0[r] + bhh0[r] + Wih0[r, 1:65] @ input[t]
__global__ void k_a0(const float* __restrict__ Wih0, const float* __restrict__ inp,
                     const float* __restrict__ bih0, const float* __restrict__ bhh0) {
    int idx = blockIdx.x * blockDim.x + threadIdx.x;   // 128*8192 threads
    int r = idx & (G4 - 1);
    int t = idx >> 13;
    float acc = bih0[r] + bhh0[r];
    const float* w = Wih0 + (size_t)r * (IN_SZ + 1) + 1;
    const float* x = inp + (size_t)t * IN_SZ;
#pragma unroll
    for (int k = 0; k < IN_SZ; k++) acc += w[k] * x[k];
    g_A0[t * G4 + r] = acc;
}

__device__ __forceinline__ float sigf(float x) { return 1.0f / (1.0f + expf(-x)); }

__device__ __forceinline__ float dot4(float4 a, float4 b) {
    return a.x * b.x + a.y * b.y + a.z * b.z + a.w * b.w;
}

// layer0: block j computes 4 gate dots (len H) + A0 + prev term, then cell update
__global__ void k_layer0(const float* __restrict__ Wih0, const float* __restrict__ Whh0,
                         int t, int ph) {
    int j = blockIdx.x;
    int w = threadIdx.x >> 5, lane = threadIdx.x & 31;
    int row = w * H + j;
    const float4* W4 = (const float4*)(Whh0 + (size_t)row * H);
    const float4* h4 = (const float4*)g_h0[ph];
    float acc = 0.f;
#pragma unroll
    for (int k = 0; k < H / 128; k++) {   // 16 iters
        float4 a = W4[lane + 32 * k];
        float4 b = h4[lane + 32 * k];
        acc += dot4(a, b);
    }
#pragma unroll
    for (int o = 16; o; o >>= 1) acc += __shfl_down_sync(0xffffffffu, acc, o);
    __shared__ float gs[4];
    if (lane == 0)
        gs[w] = acc + g_A0[t * G4 + row] + Wih0[(size_t)row * (IN_SZ + 1)] * g_prev;
    __syncthreads();
    if (threadIdx.x == 0) {
        float gi = gs[0], gf = gs[1], gg = gs[2], go = gs[3];
        float c = sigf(gf) * g_c0[j] + sigf(gi) * tanhf(gg);
        g_c0[j] = c;
        g_h0[ph ^ 1][j] = sigf(go) * tanhf(c);
    }
}

// layer1: block j computes 4 gates = Wih1@h0new + Whh1@h1old + biases, cell update
__global__ void k_layer1(const float* __restrict__ Wih1, const float* __restrict__ Whh1,
                         const float* __restrict__ bih1, const float* __restrict__ bhh1,
                         int ph) {
    int j = blockIdx.x;
    int w = threadIdx.x >> 5, lane = threadIdx.x & 31;
    int row = w * H + j;
    const float4* Wa = (const float4*)(Wih1 + (size_t)row * H);
    const float4* Wb = (const float4*)(Whh1 + (size_t)row * H);
    const float4* ha = (const float4*)g_h0[ph ^ 1];  // new h0 from layer0 this step
    const float4* hb = (const float4*)g_h1[ph];      // previous-step h1
    float acc = 0.f;
#pragma unroll
    for (int k = 0; k < H / 128; k++) {
        float4 a = Wa[lane + 32 * k];
        float4 b = ha[lane + 32 * k];
        acc += dot4(a, b);
    }
#pragma unroll
    for (int k = 0; k < H / 128; k++) {
        float4 a = Wb[lane + 32 * k];
        float4 b = hb[lane + 32 * k];
        acc += dot4(a, b);
    }
#pragma unroll
    for (int o = 16; o; o >>= 1) acc += __shfl_down_sync(0xffffffffu, acc, o);
    __shared__ float gs[4];
    if (lane == 0) gs[w] = acc + bih1[row] + bhh1[row];
    __syncthreads();
    if (threadIdx.x == 0) {
        float gi = gs[0], gf = gs[1], gg = gs[2], go = gs[3];
        float c = sigf(gf) * g_c1[j] + sigf(gi) * tanhf(gg);
        g_c1[j] = c;
        g_h1[ph ^ 1][j] = sigf(go) * tanhf(c);
    }
}

// logits: warp per output row; also writes gumbel-perturbed logits
__global__ void k_logits(const float* __restrict__ Wl, const float* __restrict__ bl,
                         int t, int ph) {
    int row = blockIdx.x * 8 + (threadIdx.x >> 5);
    int lane = threadIdx.x & 31;
    const float4* W4 = (const float4*)(Wl + (size_t)row * H);
    const float4* h4 = (const float4*)g_h1[ph ^ 1];
    float acc = 0.f;
#pragma unroll
    for (int k = 0; k < H / 128; k++) {
        float4 a = W4[lane + 32 * k];
        float4 b = h4[lane + 32 * k];
        acc += dot4(a, b);
    }
#pragma unroll
    for (int o = 16; o; o >>= 1) acc += __shfl_down_sync(0xffffffffu, acc, o);
    if (lane == 0) {
        float lg = acc + bl[row];
        g_logits[row] = lg;
        g_pert[row]   = lg + g_gum[t * OUT_SZ + row];
    }
}

// single block: argmax(perturbed) -> sample; softmax(logits) -> probs; feedback prev
__global__ void k_sample(int t, float* __restrict__ out) {
    const int tid = threadIdx.x;  // 1024 threads
    const unsigned full = 0xffffffffu;
    float bm = -CUDART_INF_F; int bi = 0; float lm = -CUDART_INF_F;
    for (int r = tid; r < OUT_SZ; r += 1024) {
        float p = g_pert[r];
        if (p > bm) { bm = p; bi = r; }
        lm = fmaxf(lm, g_logits[r]);
    }
#pragma unroll
    for (int o = 16; o; o >>= 1) {
        float om = __shfl_down_sync(full, bm, o);
        int   oi = __shfl_down_sync(full, bi, o);
        float ol = __shfl_down_sync(full, lm, o);
        if (om > bm || (om == bm && oi < bi)) { bm = om; bi = oi; }
        lm = fmaxf(lm, ol);
    }
    __shared__ float smx[32]; __shared__ int six[32]; __shared__ float slx[32];
    __shared__ float sM; __shared__ int sI; __shared__ float sS;
    int w = tid >> 5, lane = tid & 31;
    if (lane == 0) { smx[w] = bm; six[w] = bi; slx[w] = lm; }
    __syncthreads();
    if (w == 0) {
        bm = smx[lane]; bi = six[lane]; lm = slx[lane];
#pragma unroll
        for (int o = 16; o; o >>= 1) {
            float om = __shfl_down_sync(full, bm, o);
            int   oi = __shfl_down_sync(full, bi, o);
            float ol = __shfl_down_sync(full, lm, o);
            if (om > bm || (om == bm && oi < bi)) { bm = om; bi = oi; }
            lm = fmaxf(lm, ol);
        }
        if (lane == 0) { sM = lm; sI = bi; }
    }
    __syncthreads();
    float M = sM;
    float s = 0.f;
    for (int r = tid; r < OUT_SZ; r += 1024) s += expf(g_logits[r] - M);
#pragma unroll
    for (int o = 16; o; o >>= 1) s += __shfl_down_sync(full, s, o);
    if (lane == 0) smx[w] = s;   // reuse smx as sum buffer (all warps past previous reads)
    __syncthreads();
    if (w == 0) {
        s = smx[lane];
#pragma unroll
        for (int o = 16; o; o >>= 1) s += __shfl_down_sync(full, s, o);
        if (lane == 0) sS = s;
    }
    __syncthreads();
    float S = sS;
    float* probs = out + T_STEPS + (size_t)t * OUT_SZ;
    for (int r = tid; r < OUT_SZ; r += 1024)
        probs[r] = expf(g_logits[r] - M) / S;
    if (tid == 0) {
        out[t] = (float)sI;
        g_prev = (float)sI;
    }
}

// ---------------- host launcher ----------------
extern "C" void kernel_launch(void* const* d_in, const int* in_sizes, int n_in,
                              void* d_out, int out_size) {
    const float* input = (const float*)d_in[0];
    const float* h0    = (const float*)d_in[1];
    const float* c0    = (const float*)d_in[2];
    const float* Wih0  = (const float*)d_in[3];
    const float* Whh0  = (const float*)d_in[4];
    const float* bih0  = (const float*)d_in[5];
    const float* bhh0  = (const float*)d_in[6];
    const float* Wih1  = (const float*)d_in[7];
    const float* Whh1  = (const float*)d_in[8];
    const float* bih1  = (const float*)d_in[9];
    const float* bhh1  = (const float*)d_in[10];
    const float* Wl    = (const float*)d_in[11];
    const float* bl    = (const float*)d_in[12];
    float* out = (float*)d_out;

    // Precompute (off the sequential critical path)
    k_keys<<<1, 128>>>();
    k_gumbel<<<(T_STEPS * OUT_SZ) / 256, 256>>>();
    k_init<<<(H + 255) / 256, 256>>>(h0, c0);
    k_a0<<<(T_STEPS * G4) / 256, 256>>>(Wih0, input, bih0, bhh0);

    // Sequential autoregressive steps
    for (int t = 0; t < T_STEPS; t++) {
        int ph = t & 1;
        k_layer0<<<H, 128>>>(Wih0, Whh0, t, ph);
        k_layer1<<<H, 128>>>(Wih1, Whh1, bih1, bhh1, ph);
        k_logits<<<OUT_SZ / 8, 256>>>(Wl, bl, t, ph);
        k_sample<<<1, 1024>>>(t, out);
    }
}

// round 2
// speedup vs baseline: 1.2007x; 1.2007x over previous
#include <cuda_runtime.h>
#include <cuda_bf16.h>
#include <cstdint>
#include <math_constants.h>

// Problem constants
#define T_STEPS 128
#define IN_SZ   64
#define H       2048
#define OUT_SZ  4096
#define G4      (4*H)   // 8192 gate rows per layer

// ---------------- device scratch (static, no runtime allocation) ----------------
__device__ __align__(16) __nv_bfloat16 g_Whh0b[G4 * H];     // 33.5 MB
__device__ __align__(16) __nv_bfloat16 g_Wih1b[G4 * H];     // 33.5 MB
__device__ __align__(16) __nv_bfloat16 g_Whh1b[G4 * H];     // 33.5 MB
__device__ __align__(16) __nv_bfloat16 g_Wlb[OUT_SZ * H];   // 16.8 MB
__device__ __align__(16) float g_A0[T_STEPS * G4];          // Wih0[:,1:]@x_t + bih0 + bhh0
__device__ __align__(16) float g_wcol0[G4];                 // Wih0[:,0]
__device__ __align__(16) float g_bsum1[G4];                 // bih1 + bhh1
__device__ __align__(16) float g_gum[T_STEPS * OUT_SZ];     // gumbel noise
__device__ uint32_t g_keys2[2 * T_STEPS];
__device__ __align__(16) float g_h0[2][H];
__device__ __align__(16) float g_h1[2][H];
__device__ __align__(16) float g_c0[H];
__device__ __align__(16) float g_c1[H];
__device__ float g_prev;
__device__ __align__(16) float g_logits[OUT_SZ];
__device__ __align__(16) float g_pert[OUT_SZ];
__device__ unsigned g_count;

// ---------------- threefry2x32 (JAX partitionable) ----------------
__device__ __forceinline__ void tf2x32(uint32_t k0, uint32_t k1, uint32_t& x0, uint32_t& x1) {
    uint32_t ks2 = k0 ^ k1 ^ 0x1BD11BDAu;
    x0 += k0; x1 += k1;
#define TF_RND(r) { x0 += x1; x1 = (x1 << (r)) | (x1 >> (32 - (r))); x1 ^= x0; }
    TF_RND(13) TF_RND(15) TF_RND(26) TF_RND(6)   x0 += k1;  x1 += ks2 + 1u;
    TF_RND(17) TF_RND(29) TF_RND(16) TF_RND(24)  x0 += ks2; x1 += k0 + 2u;
    TF_RND(13) TF_RND(15) TF_RND(26) TF_RND(6)   x0 += k0;  x1 += k1 + 3u;
    TF_RND(17) TF_RND(29) TF_RND(16) TF_RND(24)  x0 += k1;  x1 += ks2 + 4u;
    TF_RND(13) TF_RND(15) TF_RND(26) TF_RND(6)   x0 += ks2; x1 += k0 + 5u;
#undef TF_RND
}

__global__ void k_keys() {
    int t = threadIdx.x;  // 128 threads
    uint32_t x0 = 0u, x1 = (uint32_t)t;
    tf2x32(0u, 42u, x0, x1);
    g_keys2[2 * t] = x0;
    g_keys2[2 * t + 1] = x1;
}

__global__ void k_gumbel() {
    int idx = blockIdx.x * blockDim.x + threadIdx.x;
    int t = idx >> 12;
    int i = idx & (OUT_SZ - 1);
    uint32_t x0 = 0u, x1 = (uint32_t)i;
    tf2x32(g_keys2[2 * t], g_keys2[2 * t + 1], x0, x1);
    uint32_t bits = x0 ^ x1;
    float f = __uint_as_float((bits >> 9) | 0x3f800000u) - 1.0f;
    const float TINY = 1.17549435e-38f;
    float u = fmaxf(f + TINY, TINY);
    g_gum[idx] = -logf(-logf(u));
}

__global__ void k_init(const float* __restrict__ h0in, const float* __restrict__ c0in) {
    int i = blockIdx.x * blockDim.x + threadIdx.x;
    if (i < H) {
        g_h0[0][i] = h0in[i];
        g_c0[i]    = c0in[i];
        g_h1[0][i] = h0in[H + i];
        g_c1[i]    = c0in[H + i];
    }
    if (i == 0) { g_prev = 1.0f; g_count = 0u; }
}

// fp32 -> bf16 weight conversion + small precomputes
__global__ void k_convert(const float* __restrict__ Whh0, const float* __restrict__ Wih1,
                          const float* __restrict__ Whh1, const float* __restrict__ Wl,
                          const float* __restrict__ Wih0,
                          const float* __restrict__ bih1, const float* __restrict__ bhh1) {
    long i = (long)blockIdx.x * blockDim.x + threadIdx.x;
    const long N1 = (long)G4 * H;
    if (i < N1) {
        g_Whh0b[i] = __float2bfloat16(Whh0[i]);
        g_Wih1b[i] = __float2bfloat16(Wih1[i]);
        g_Whh1b[i] = __float2bfloat16(Whh1[i]);
    }
    if (i < (long)OUT_SZ * H) g_Wlb[i] = __float2bfloat16(Wl[i]);
    if (i < G4) {
        g_wcol0[i] = Wih0[i * (IN_SZ + 1)];
        g_bsum1[i] = bih1[i] + bhh1[i];
    }
}

// A0[t][r] = bih0[r] + bhh0[r] + Wih0[r, 1:65] @ input[t]
__global__ void k_a0(const float* __restrict__ Wih0, const float* __restrict__ inp,
                     const float* __restrict__ bih0, const float* __restrict__ bhh0) {
    int idx = blockIdx.x * blockDim.x + threadIdx.x;
    int r = idx & (G4 - 1);
    int t = idx >> 13;
    float acc = bih0[r] + bhh0[r];
    const float* w = Wih0 + (size_t)r * (IN_SZ + 1) + 1;
    const float* x = inp + (size_t)t * IN_SZ;
#pragma unroll
    for (int k = 0; k < IN_SZ; k++) acc += w[k] * x[k];
    g_A0[t * G4 + r] = acc;
}

__device__ __forceinline__ float sigf(float x) { return 1.0f / (1.0f + expf(-x)); }

// dot of 8 bf16 (packed in uint4) with 8 fp32 (two float4), fp32 accumulate
__device__ __forceinline__ float bfdot8(uint4 w, float4 a, float4 b) {
    __nv_bfloat162 p;
    float s;
    p = *(__nv_bfloat162*)&w.x; s  = __bfloat162float(p.x) * a.x + __bfloat162float(p.y) * a.y;
    p = *(__nv_bfloat162*)&w.y; s += __bfloat162float(p.x) * a.z + __bfloat162float(p.y) * a.w;
    p = *(__nv_bfloat162*)&w.z; s += __bfloat162float(p.x) * b.x + __bfloat162float(p.y) * b.y;
    p = *(__nv_bfloat162*)&w.w; s += __bfloat162float(p.x) * b.z + __bfloat162float(p.y) * b.w;
    return s;
}

// layer0: 512 blocks x 512 threads. Block handles 4 gate-columns; each column gets
// 4 warps (K-chunks of 512). 8-lane groups per gate row. Cell update fused in-block.
__global__ void __launch_bounds__(512) k_l0(int t, int ph) {
    int warp = threadIdx.x >> 5, lane = threadIdx.x & 31;
    int colb = warp >> 2;                 // 0..3 column within block
    int q = warp & 3;                     // K chunk
    int j = (blockIdx.x << 2) + colb;     // global column
    int g = lane >> 3, l8 = lane & 7;     // gate group, lane in group
    int row = g * H + j;
    const uint4* W = (const uint4*)(g_Whh0b + (size_t)row * H + q * 512);
    const float4* hb = (const float4*)(g_h0[ph] + q * 512);
    float acc = 0.f;
#pragma unroll
    for (int i = 0; i < 8; i++) {
        uint4 w = W[i * 8 + l8];
        float4 a = hb[(i * 8 + l8) * 2];
        float4 b = hb[(i * 8 + l8) * 2 + 1];
        acc += bfdot8(w, a, b);
    }
    acc += __shfl_down_sync(0xffffffffu, acc, 4);
    acc += __shfl_down_sync(0xffffffffu, acc, 2);
    acc += __shfl_down_sync(0xffffffffu, acc, 1);
    __shared__ float part[4][4][4];       // [col][gate][chunk]
    if (l8 == 0) part[colb][g][q] = acc;
    __syncthreads();
    if (threadIdx.x < 4) {
        int jj = (blockIdx.x << 2) + threadIdx.x;
        float prev = g_prev;
        float gg[4];
#pragma unroll
        for (int gi = 0; gi < 4; gi++) {
            int rr = gi * H + jj;
            gg[gi] = part[threadIdx.x][gi][0] + part[threadIdx.x][gi][1]
                   + part[threadIdx.x][gi][2] + part[threadIdx.x][gi][3]
                   + g_A0[t * G4 + rr] + g_wcol0[rr] * prev;
        }
        float c = sigf(gg[1]) * g_c0[jj] + sigf(gg[0]) * tanhf(gg[2]);
        g_c0[jj] = c;
        g_h0[ph ^ 1][jj] = sigf(gg[3]) * tanhf(c);
    }
}

// layer1: same structure, two weight matrices (Wih1 @ h0_new + Whh1 @ h1_old)
__global__ void __launch_bounds__(512) k_l1(int ph) {
    int warp = threadIdx.x >> 5, lane = threadIdx.x & 31;
    int colb = warp >> 2;
    int q = warp & 3;
    int j = (blockIdx.x << 2) + colb;
    int g = lane >> 3, l8 = lane & 7;
    int row = g * H + j;
    const uint4* Wa = (const uint4*)(g_Wih1b + (size_t)row * H + q * 512);
    const uint4* Wb = (const uint4*)(g_Whh1b + (size_t)row * H + q * 512);
    const float4* ha = (const float4*)(g_h0[ph ^ 1] + q * 512);
    const float4* hb = (const float4*)(g_h1[ph] + q * 512);
    float acc = 0.f;
#pragma unroll
    for (int i = 0; i < 8; i++) {
        uint4 w = Wa[i * 8 + l8];
        float4 a = ha[(i * 8 + l8) * 2];
        float4 b = ha[(i * 8 + l8) * 2 + 1];
        acc += bfdot8(w, a, b);
    }
#pragma unroll
    for (int i = 0; i < 8; i++) {
        uint4 w = Wb[i * 8 + l8];
        float4 a = hb[(i * 8 + l8) * 2];
        float4 b = hb[(i * 8 + l8) * 2 + 1];
        acc += bfdot8(w, a, b);
    }
    acc += __shfl_down_sync(0xffffffffu, acc, 4);
    acc += __shfl_down_sync(0xffffffffu, acc, 2);
    acc += __shfl_down_sync(0xffffffffu, acc, 1);
    __shared__ float part[4][4][4];
    if (l8 == 0) part[colb][g][q] = acc;
    __syncthreads();
    if (threadIdx.x < 4) {
        int jj = (blockIdx.x << 2) + threadIdx.x;
        float gg[4];
#pragma unroll
        for (int gi = 0; gi < 4; gi++) {
            int rr = gi * H + jj;
            gg[gi] = part[threadIdx.x][gi][0] + part[threadIdx.x][gi][1]
                   + part[threadIdx.x][gi][2] + part[threadIdx.x][gi][3]
                   + g_bsum1[rr];
        }
        float c = sigf(gg[1]) * g_c1[jj] + sigf(gg[0]) * tanhf(gg[2]);
        g_c1[jj] = c;
        g_h1[ph ^ 1][jj] = sigf(gg[3]) * tanhf(c);
    }
}

// logits + gumbel perturbation + fused last-block sampler/softmax
// 256 blocks x 512 threads; warp per output row (16 rows/block)
__global__ void __launch_bounds__(512) k_logits(const float* __restrict__ bl,
                                                int t, int ph, float* __restrict__ out) {
    int warp = threadIdx.x >> 5, lane = threadIdx.x & 31;
    int r = (blockIdx.x << 4) + warp;
    const uint4* W = (const uint4*)(g_Wlb + (size_t)r * H);
    const float4* hb = (const float4*)g_h1[ph ^ 1];
    float acc = 0.f;
#pragma unroll
    for (int i = 0; i < 8; i++) {
        int idx = i * 32 + lane;
        uint4 w = W[idx];
        float4 a = hb[idx * 2];
        float4 b = hb[idx * 2 + 1];
        acc += bfdot8(w, a, b);
    }
#pragma unroll
    for (int o = 16; o; o >>= 1) acc += __shfl_down_sync(0xffffffffu, acc, o);
    if (lane == 0) {
        float lg = acc + bl[r];
        g_logits[r] = lg;
        g_pert[r] = lg + g_gum[t * OUT_SZ + r];
    }

    // ---- last-block sampler ----
    __shared__ bool s_last;
    __syncthreads();
    if (threadIdx.x == 0) {
        __threadfence();
        unsigned v = atomicAdd(&g_count, 1u);
        s_last = (v == gridDim.x - 1);
    }
    __syncthreads();
    if (!s_last) return;

    const unsigned full = 0xffffffffu;
    int tid = threadIdx.x;
    float bm = -CUDART_INF_F; int bi = 0; float lm = -CUDART_INF_F;
    for (int rr = tid; rr < OUT_SZ; rr += 512) {
        float p = g_pert[rr];
        if (p > bm) { bm = p; bi = rr; }
        lm = fmaxf(lm, g_logits[rr]);
    }
#pragma unroll
    for (int o = 16; o; o >>= 1) {
        float om = __shfl_down_sync(full, bm, o);
        int   oi = __shfl_down_sync(full, bi, o);
        float ol = __shfl_down_sync(full, lm, o);
        if (om > bm || (om == bm && oi < bi)) { bm = om; bi = oi; }
        lm = fmaxf(lm, ol);
    }
    __shared__ float smx[16]; __shared__ int six[16]; __shared__ float slx[16];
    __shared__ float sM, sS; __shared__ int sI;
    if (lane == 0) { smx[warp] = bm; six[warp] = bi; slx[warp] = lm; }
    __syncthreads();
    if (warp == 0) {
        if (lane < 16) { bm = smx[lane]; bi = six[lane]; lm = slx[lane]; }
        else { bm = -CUDART_INF_F; bi = 1 << 30; lm = -CUDART_INF_F; }
#pragma unroll
        for (int o = 8; o; o >>= 1) {
            float om = __shfl_down_sync(full, bm, o);
            int   oi = __shfl_down_sync(full, bi, o);
            float ol = __shfl_down_sync(full, lm, o);
            if (om > bm || (om == bm && oi < bi)) { bm = om; bi = oi; }
            lm = fmaxf(lm, ol);
        }
        if (lane == 0) { sM = lm; sI = bi; }
    }
    __syncthreads();
    float M = sM;
    float s = 0.f;
    for (int rr = tid; rr < OUT_SZ; rr += 512) s += expf(g_logits[rr] - M);
#pragma unroll
    for (int o = 16; o; o >>= 1) s += __shfl_down_sync(full, s, o);
    if (lane == 0) smx[warp] = s;
    __syncthreads();
    if (warp == 0) {
        s = (lane < 16) ? smx[lane] : 0.f;
#pragma unroll
        for (int o = 8; o; o >>= 1) s += __shfl_down_sync(full, s, o);
        if (lane == 0) sS = s;
    }
    __syncthreads();
    float S = sS;
    float* probs = out + T_STEPS + (size_t)t * OUT_SZ;
    for (int rr = tid; rr < OUT_SZ; rr += 512)
        probs[rr] = expf(g_logits[rr] - M) / S;
    if (tid == 0) {
        out[t] = (float)sI;
        g_prev = (float)sI;
        g_count = 0u;
    }
}

// ---------------- host launcher ----------------
extern "C" void kernel_launch(void* const* d_in, const int* in_sizes, int n_in,
                              void* d_out, int out_size) {
    const float* input = (const float*)d_in[0];
    const float* h0    = (const float*)d_in[1];
    const float* c0    = (const float*)d_in[2];
    const float* Wih0  = (const float*)d_in[3];
    const float* Whh0  = (const float*)d_in[4];
    const float* bih0  = (const float*)d_in[5];
    const float* bhh0  = (const float*)d_in[6];
    const float* Wih1  = (const float*)d_in[7];
    const float* Whh1  = (const float*)d_in[8];
    const float* bih1  = (const float*)d_in[9];
    const float* bhh1  = (const float*)d_in[10];
    const float* Wl    = (const float*)d_in[11];
    const float* bl    = (const float*)d_in[12];
    float* out = (float*)d_out;

    // Precompute (off the sequential critical path)
    k_convert<<<(G4 * H + 255) / 256, 256>>>(Whh0, Wih1, Whh1, Wl, Wih0, bih1, bhh1);
    k_keys<<<1, 128>>>();
    k_gumbel<<<(T_STEPS * OUT_SZ) / 256, 256>>>();
    k_init<<<(H + 255) / 256, 256>>>(h0, c0);
    k_a0<<<(T_STEPS * G4) / 256, 256>>>(Wih0, input, bih0, bhh0);

    // Sequential autoregressive steps: 3 launches per step
    for (int t = 0; t < T_STEPS; t++) {
        int ph = t & 1;
        k_l0<<<512, 512>>>(t, ph);
        k_l1<<<512, 512>>>(ph);
        k_logits<<<256, 512>>>(bl, t, ph, out);
    }
}

// round 4
// speedup vs baseline: 1.6858x; 1.4040x over previous
#include <cuda_runtime.h>
#include <cuda_bf16.h>
#include <cstdint>
#include <math_constants.h>

// Problem constants
#define T_STEPS 128
#define IN_SZ   64
#define H       2048
#define OUT_SZ  4096
#define G4      (4*H)

// Persistent kernel config
#define NBLK 128
#define NTHR 512
#define COLS_PER_BLK 16          // hidden columns per block (128*16 = 2048)
#define SMEM_COLS 12             // columns whose Whh0 rows live in smem
#define SMEM_W_BYTES (SMEM_COLS * 4 * H * 2)        // 192 KB
#define SMEM_BYTES   (SMEM_W_BYTES + 2 * H * 4)     // + 16 KB h stage = 208 KB

// ---------------- device scratch ----------------
__device__ __align__(16) __nv_bfloat16 g_Whh0b[G4 * H];
__device__ __align__(16) __nv_bfloat16 g_Wih1b[G4 * H];
__device__ __align__(16) __nv_bfloat16 g_Whh1b[G4 * H];
__device__ __align__(16) __nv_bfloat16 g_Wlb[OUT_SZ * H];
__device__ __align__(16) float g_A0[T_STEPS * G4];
__device__ __align__(16) float g_wcol0[G4];
__device__ __align__(16) float g_bsum1[G4];
__device__ __align__(16) float g_gum[T_STEPS * OUT_SZ];
__device__ uint32_t g_keys2[2 * T_STEPS];
__device__ __align__(16) float g_h0[2][H];
__device__ __align__(16) float g_h1[2][H];
__device__ __align__(16) float g_c0[H];
__device__ __align__(16) float g_c1[H];
__device__ float g_prev;
__device__ float g_M, g_S;
__device__ float g_bm[NBLK], g_blm[NBLK], g_bs[NBLK];
__device__ int   g_bi[NBLK];
__device__ unsigned g_cnt;
__device__ volatile unsigned g_epoch;

// ---------------- threefry2x32 (JAX partitionable) ----------------
__device__ __forceinline__ void tf2x32(uint32_t k0, uint32_t k1, uint32_t& x0, uint32_t& x1) {
    uint32_t ks2 = k0 ^ k1 ^ 0x1BD11BDAu;
    x0 += k0; x1 += k1;
#define TF_RND(r) { x0 += x1; x1 = (x1 << (r)) | (x1 >> (32 - (r))); x1 ^= x0; }
    TF_RND(13) TF_RND(15) TF_RND(26) TF_RND(6)   x0 += k1;  x1 += ks2 + 1u;
    TF_RND(17) TF_RND(29) TF_RND(16) TF_RND(24)  x0 += ks2; x1 += k0 + 2u;
    TF_RND(13) TF_RND(15) TF_RND(26) TF_RND(6)   x0 += k0;  x1 += k1 + 3u;
    TF_RND(17) TF_RND(29) TF_RND(16) TF_RND(24)  x0 += k1;  x1 += ks2 + 4u;
    TF_RND(13) TF_RND(15) TF_RND(26) TF_RND(6)   x0 += ks2; x1 += k0 + 5u;
#undef TF_RND
}

__global__ void k_keys() {
    int t = threadIdx.x;
    uint32_t x0 = 0u, x1 = (uint32_t)t;
    tf2x32(0u, 42u, x0, x1);
    g_keys2[2 * t] = x0;
    g_keys2[2 * t + 1] = x1;
}

__global__ void k_gumbel() {
    int idx = blockIdx.x * blockDim.x + threadIdx.x;
    int t = idx >> 12;
    int i = idx & (OUT_SZ - 1);
    uint32_t x0 = 0u, x1 = (uint32_t)i;
    tf2x32(g_keys2[2 * t], g_keys2[2 * t + 1], x0, x1);
    uint32_t bits = x0 ^ x1;
    float f = __uint_as_float((bits >> 9) | 0x3f800000u) - 1.0f;
    const float TINY = 1.17549435e-38f;
    float u = fmaxf(f + TINY, TINY);
    g_gum[idx] = -logf(-logf(u));
}

__global__ void k_init(const float* __restrict__ h0in, const float* __restrict__ c0in) {
    int i = blockIdx.x * blockDim.x + threadIdx.x;
    if (i < H) {
        g_h0[0][i] = h0in[i];
        g_c0[i]    = c0in[i];
        g_h1[0][i] = h0in[H + i];
        g_c1[i]    = c0in[H + i];
    }
    if (i == 0) { g_prev = 1.0f; g_cnt = 0u; g_epoch = 0u; }
}

__global__ void k_convert(const float* __restrict__ Whh0, const float* __restrict__ Wih1,
                          const float* __restrict__ Whh1, const float* __restrict__ Wl,
                          const float* __restrict__ Wih0,
                          const float* __restrict__ bih1, const float* __restrict__ bhh1) {
    long i = (long)blockIdx.x * blockDim.x + threadIdx.x;
    const long N1 = (long)G4 * H;
    if (i < N1) {
        g_Whh0b[i] = __float2bfloat16(Whh0[i]);
        g_Wih1b[i] = __float2bfloat16(Wih1[i]);
        g_Whh1b[i] = __float2bfloat16(Whh1[i]);
    }
    if (i < (long)OUT_SZ * H) g_Wlb[i] = __float2bfloat16(Wl[i]);
    if (i < G4) {
        g_wcol0[i] = Wih0[i * (IN_SZ + 1)];
        g_bsum1[i] = bih1[i] + bhh1[i];
    }
}

__global__ void k_a0(const float* __restrict__ Wih0, const float* __restrict__ inp,
                     const float* __restrict__ bih0, const float* __restrict__ bhh0) {
    int idx = blockIdx.x * blockDim.x + threadIdx.x;
    int r = idx & (G4 - 1);
    int t = idx >> 13;
    float acc = bih0[r] + bhh0[r];
    const float* w = Wih0 + (size_t)r * (IN_SZ + 1) + 1;
    const float* x = inp + (size_t)t * IN_SZ;
#pragma unroll
    for (int k = 0; k < IN_SZ; k++) acc += w[k] * x[k];
    g_A0[t * G4 + r] = acc;
}

__device__ __forceinline__ float sigf(float x) { return 1.0f / (1.0f + expf(-x)); }
__device__ __forceinline__ float blo(uint32_t u) { return __uint_as_float(u << 16); }
__device__ __forceinline__ float bhi(uint32_t u) { return __uint_as_float(u & 0xffff0000u); }

// dot of 8 bf16 (uint4) with 8 fp32; bf16->fp32 via exact integer shifts (full-rate ALU)
__device__ __forceinline__ float bfdot8(uint4 w, float4 a, float4 b) {
    return blo(w.x) * a.x + bhi(w.x) * a.y
         + blo(w.y) * a.z + bhi(w.y) * a.w
         + blo(w.z) * b.x + bhi(w.z) * b.y
         + blo(w.w) * b.z + bhi(w.w) * b.w;
}

__device__ __forceinline__ float warp_sum(float v) {
#pragma unroll
    for (int o = 16; o; o >>= 1) v += __shfl_down_sync(0xffffffffu, v, o);
    return v;
}

// grid-wide barrier (all NBLK blocks co-resident by construction)
__device__ __forceinline__ void gbar(unsigned target) {
    __syncthreads();
    if (threadIdx.x == 0) {
        __threadfence();
        unsigned a = atomicAdd(&g_cnt, 1u);
        if (a == NBLK - 1u) {
            g_cnt = 0u;
            __threadfence();
            g_epoch = target;
        } else {
            while (g_epoch < target) {}
        }
    }
    __syncthreads();
}

__global__ void __launch_bounds__(NTHR, 1) k_persist(const float* __restrict__ bl,
                                                     float* __restrict__ out) {
    extern __shared__ char smem[];
    __nv_bfloat16* ws = (__nv_bfloat16*)smem;            // 48 rows x 2048 bf16
    float* hs = (float*)(smem + SMEM_W_BYTES);           // up to 2 x 2048 fp32
    __shared__ float sg[64];
    __shared__ float slog[32], sper[32];
    __shared__ unsigned s_rank;
    __shared__ float rm[4], rlm[4], rs[4], s_Mv;
    __shared__ int rix[4], s_Iv;

    const int tid  = threadIdx.x;
    const int warp = tid >> 5, lane = tid & 31;
    const int b = blockIdx.x;
    const int c0 = b * COLS_PER_BLK;

    // ---- load Whh0 slice into smem (rows: slot = j*4+g, j<SMEM_COLS) ----
    for (int slot = warp; slot < SMEM_COLS * 4; slot += 16) {
        int j = slot >> 2, g = slot & 3;
        const uint4* src = (const uint4*)(g_Whh0b + ((size_t)(g * H + c0 + j)) * H);
        uint4* dst = (uint4*)(ws + (size_t)slot * H);
        for (int i = lane; i < H / 8; i += 32) dst[i] = src[i];
    }

    for (int t = 0; t < T_STEPS; t++) {
        int ph = t & 1;

        // ---- stage h0_old into smem (L1-bypass: cross-block data) ----
        __syncthreads();
        {
            const float4* src = (const float4*)g_h0[ph];
            float4* dst = (float4*)hs;
            for (int i = tid; i < H / 4; i += NTHR) dst[i] = __ldcg(src + i);
        }
        __syncthreads();

        // ---- layer0 gate dots (no dependence on sample(t-1)) ----
#pragma unroll
        for (int p = 0; p < 4; p++) {
            int ri = p * 16 + warp;          // 0..63
            int j = ri >> 2, g = ri & 3;
            const uint4* W = (j < SMEM_COLS)
                ? (const uint4*)(ws + (size_t)ri * H)
                : (const uint4*)(g_Whh0b + ((size_t)(g * H + c0 + j)) * H);
            const float4* hv = (const float4*)hs;
            float acc = 0.f;
#pragma unroll
            for (int i = 0; i < 8; i++) {
                uint4 w = W[i * 32 + lane];
                float4 a  = hv[(i * 32 + lane) * 2];
                float4 b2 = hv[(i * 32 + lane) * 2 + 1];
                acc += bfdot8(w, a, b2);
            }
            acc = warp_sum(acc);
            if (lane == 0) sg[ri] = acc;
        }

        // ---- deferred wait: sampler(t-1) done; then probs(t-1) + cell0 ----
        if (tid == 0) { while (g_epoch < (unsigned)(3 * t)) {} }
        __syncthreads();
        if (t > 0) {
            float M = __ldcg(&g_M), S = __ldcg(&g_S);
            if (tid < 32)
                out[T_STEPS + (size_t)(t - 1) * OUT_SZ + b * 32 + tid] =
                    expf(slog[tid] - M) / S;
        }
        if (tid < COLS_PER_BLK) {
            int j = tid, col = c0 + j;
            float prev = __ldcg(&g_prev);
            float gg[4];
#pragma unroll
            for (int g = 0; g < 4; g++) {
                int r = g * H + col;
                gg[g] = sg[j * 4 + g] + g_A0[t * G4 + r] + g_wcol0[r] * prev;
            }
            float c = sigf(gg[1]) * g_c0[col] + sigf(gg[0]) * tanhf(gg[2]);
            g_c0[col] = c;
            __stcg(&g_h0[ph ^ 1][col], sigf(gg[3]) * tanhf(c));
            __threadfence();
        }
        gbar((unsigned)(3 * t + 1));

        // ---- stage ha = h0_new, hb = h1_old ----
        {
            const float4* sa = (const float4*)g_h0[ph ^ 1];
            const float4* sb = (const float4*)g_h1[ph];
            float4* dst = (float4*)hs;
            for (int i = tid; i < H / 4; i += NTHR) dst[i] = __ldcg(sa + i);
            for (int i = tid; i < H / 4; i += NTHR) dst[H / 4 + i] = __ldcg(sb + i);
        }
        __syncthreads();

        // ---- layer1 gate dots ----
#pragma unroll
        for (int p = 0; p < 4; p++) {
            int ri = p * 16 + warp;
            int j = ri >> 2, g = ri & 3;
            size_t off = ((size_t)(g * H + c0 + j)) * H;
            const uint4* Wa = (const uint4*)(g_Wih1b + off);
            const uint4* Wb = (const uint4*)(g_Whh1b + off);
            const float4* ha = (const float4*)hs;
            const float4* hb = (const float4*)hs + (H / 4);  // h1_old staged at float4 index H/4
            float acc = 0.f;
#pragma unroll
            for (int i = 0; i < 8; i++) {
                uint4 w = Wa[i * 32 + lane];
                acc += bfdot8(w, ha[(i * 32 + lane) * 2], ha[(i * 32 + lane) * 2 + 1]);
            }
#pragma unroll
            for (int i = 0; i < 8; i++) {
                uint4 w = Wb[i * 32 + lane];
                acc += bfdot8(w, hb[(i * 32 + lane) * 2], hb[(i * 32 + lane) * 2 + 1]);
            }
            acc = warp_sum(acc);
            if (lane == 0) sg[ri] = acc;
        }
        __syncthreads();
        if (tid < COLS_PER_BLK) {
            int j = tid, col = c0 + j;
            float gg[4];
#pragma unroll
            for (int g = 0; g < 4; g++) {
                int r = g * H + col;
                gg[g] = sg[j * 4 + g] + g_bsum1[r];
            }
            float c = sigf(gg[1]) * g_c1[col] + sigf(gg[0]) * tanhf(gg[2]);
            g_c1[col] = c;
            __stcg(&g_h1[ph ^ 1][col], sigf(gg[3]) * tanhf(c));
            __threadfence();
        }
        gbar((unsigned)(3 * t + 2));

        // ---- stage h1_new; logits for this block's 32 rows ----
        {
            const float4* src = (const float4*)g_h1[ph ^ 1];
            float4* dst = (float4*)hs;
            for (int i = tid; i < H / 4; i += NTHR) dst[i] = __ldcg(src + i);
        }
        __syncthreads();
#pragma unroll
        for (int p = 0; p < 2; p++) {
            int s = p * 16 + warp;          // 0..31
            int r = b * 32 + s;
            const uint4* W = (const uint4*)(g_Wlb + (size_t)r * H);
            const float4* hv = (const float4*)hs;
            float acc = 0.f;
#pragma unroll
            for (int i = 0; i < 8; i++) {
                uint4 w = W[i * 32 + lane];
                acc += bfdot8(w, hv[(i * 32 + lane) * 2], hv[(i * 32 + lane) * 2 + 1]);
            }
            acc = warp_sum(acc);
            if (lane == 0) {
                float lg = acc + bl[r];
                slog[s] = lg;
                sper[s] = lg + g_gum[t * OUT_SZ + r];
            }
        }
        __syncthreads();

        // ---- block-local softmax/argmax partials (online-softmax style) ----
        if (warp == 0) {
            float lg = slog[lane], pp = sper[lane];
            int idx = b * 32 + lane;
            float bm = pp; int bi = idx; float lm = lg;
#pragma unroll
            for (int o = 16; o; o >>= 1) {
                float om = __shfl_down_sync(0xffffffffu, bm, o);
                int   oi = __shfl_down_sync(0xffffffffu, bi, o);
                float ol = __shfl_down_sync(0xffffffffu, lm, o);
                if (om > bm || (om == bm && oi < bi)) { bm = om; bi = oi; }
                lm = fmaxf(lm, ol);
            }
            lm = __shfl_sync(0xffffffffu, lm, 0);
            float e = expf(lg - lm);
            e = warp_sum(e);
            if (lane == 0) {
                __stcg(&g_bm[b], bm);
                __stcg(&g_bi[b], bi);
                __stcg(&g_blm[b], lm);
                __stcg(&g_bs[b], e);
            }
        }
        __syncthreads();

        // ---- bar3 arrival; last-arriving block combines + releases ----
        if (tid == 0) {
            __threadfence();
            s_rank = atomicAdd(&g_cnt, 1u);
        }
        __syncthreads();
        if (s_rank == NBLK - 1u) {
            __threadfence();
            if (tid < NBLK) {
                float pm = __ldcg(&g_bm[tid]);
                int   pi = __ldcg(&g_bi[tid]);
                float lm = __ldcg(&g_blm[tid]);
#pragma unroll
                for (int o = 16; o; o >>= 1) {
                    float om = __shfl_down_sync(0xffffffffu, pm, o);
                    int   oi = __shfl_down_sync(0xffffffffu, pi, o);
                    float ol = __shfl_down_sync(0xffffffffu, lm, o);
                    if (om > pm || (om == pm && oi < pi)) { pm = om; pi = oi; }
                    lm = fmaxf(lm, ol);
                }
                if (lane == 0) { rm[warp] = pm; rix[warp] = pi; rlm[warp] = lm; }
            }
            __syncthreads();
            if (tid == 0) {
                float pm = rm[0]; int pi = rix[0]; float lm = rlm[0];
#pragma unroll
                for (int w = 1; w < 4; w++) {
                    if (rm[w] > pm || (rm[w] == pm && rix[w] < pi)) { pm = rm[w]; pi = rix[w]; }
                    lm = fmaxf(lm, rlm[w]);
                }
                s_Mv = lm; s_Iv = pi;
            }
            __syncthreads();
            float M = s_Mv;
            if (tid < NBLK) {
                float contrib = __ldcg(&g_bs[tid]) * expf(__ldcg(&g_blm[tid]) - M);
                contrib = warp_sum(contrib);
                if (lane == 0) rs[warp] = contrib;
            }
            __syncthreads();
            if (tid == 0) {
                float S = rs[0] + rs[1] + rs[2] + rs[3];
                out[t] = (float)s_Iv;
                __stcg(&g_prev, (float)s_Iv);
                __stcg(&g_M, M);
                __stcg(&g_S, S);
                g_cnt = 0u;
                __threadfence();
                g_epoch = (unsigned)(3 * t + 3);
            }
            __syncthreads();
        }
        // no wait here: deferred into next step (or final drain below)
    }

    // ---- final: wait for last sampler, write probs(T-1) ----
    if (tid == 0) { while (g_epoch < (unsigned)(3 * T_STEPS)) {} }
    __syncthreads();
    {
        float M = __ldcg(&g_M), S = __ldcg(&g_S);
        if (tid < 32)
            out[T_STEPS + (size_t)(T_STEPS - 1) * OUT_SZ + b * 32 + tid] =
                expf(slog[tid] - M) / S;
    }
}

// ---------------- host launcher ----------------
extern "C" void kernel_launch(void* const* d_in, const int* in_sizes, int n_in,
                              void* d_out, int out_size) {
    const float* input = (const float*)d_in[0];
    const float* h0    = (const float*)d_in[1];
    const float* c0    = (const float*)d_in[2];
    const float* Wih0  = (const float*)d_in[3];
    const float* Whh0  = (const float*)d_in[4];
    const float* bih0  = (const float*)d_in[5];
    const float* bhh0  = (const float*)d_in[6];
    const float* Wih1  = (const float*)d_in[7];
    const float* Whh1  = (const float*)d_in[8];
    const float* bih1  = (const float*)d_in[9];
    const float* bhh1  = (const float*)d_in[10];
    const float* Wl    = (const float*)d_in[11];
    const float* bl    = (const float*)d_in[12];
    float* out = (float*)d_out;

    cudaFuncSetAttribute(k_persist, cudaFuncAttributeMaxDynamicSharedMemorySize, SMEM_BYTES);

    // Precompute (parallel, off the sequential critical path)
    k_convert<<<(G4 * H + 255) / 256, 256>>>(Whh0, Wih1, Whh1, Wl, Wih0, bih1, bhh1);
    k_keys<<<1, 128>>>();
    k_gumbel<<<(T_STEPS * OUT_SZ) / 256, 256>>>();
    k_init<<<(H + 255) / 256, 256>>>(h0, c0);
    k_a0<<<(T_STEPS * G4) / 256, 256>>>(Wih0, input, bih0, bhh0);

    // Single persistent kernel runs all 128 autoregressive steps
    k_persist<<<NBLK, NTHR, SMEM_BYTES>>>(bl, out);
}

// round 5
// speedup vs baseline: 2.6103x; 1.5484x over previous
#include <cuda_runtime.h>
#include <cuda_bf16.h>
#include <cstdint>
#include <math_constants.h>

// Problem constants
#define T_STEPS 128
#define IN_SZ   64
#define H       2048
#define OUT_SZ  4096
#define G4      (4*H)

// Persistent kernel config
#define NBLK_W 128               // worker blocks
#define GRID   (NBLK_W + 1)      // + 1 dedicated sampler block
#define NTHR 512
#define COLS_PER_BLK 16
#define SMEM_COLS 12             // columns whose Whh0 rows live in smem
#define SMEM_W_BYTES (SMEM_COLS * 4 * H * 2)        // 192 KB
#define SMEM_BYTES   (SMEM_W_BYTES + 2 * H * 4)     // + 16 KB h stage = 208 KB

// ---------------- device scratch ----------------
__device__ __align__(16) __nv_bfloat16 g_Whh0b[G4 * H];
__device__ __align__(16) __nv_bfloat16 g_Wih1b[G4 * H];
__device__ __align__(16) __nv_bfloat16 g_Whh1b[G4 * H];
__device__ __align__(16) __nv_bfloat16 g_Wlb[OUT_SZ * H];
__device__ __align__(16) float g_A0[T_STEPS * G4];
__device__ __align__(16) float g_wcol0[G4];
__device__ __align__(16) float g_bsum1[G4];
__device__ __align__(16) float g_gum[T_STEPS * OUT_SZ];
__device__ uint32_t g_keys2[2 * T_STEPS];
__device__ __align__(16) float g_h0[2][H];
__device__ __align__(16) float g_h1[2][H];
__device__ __align__(16) float g_c0[H];
__device__ __align__(16) float g_c1[H];
__device__ float g_prev;
__device__ float g_M, g_S;
__device__ float g_bm[NBLK_W], g_blm[NBLK_W], g_bs[NBLK_W];
__device__ int   g_bi[NBLK_W];
__device__ unsigned g_cnt;
__device__ volatile unsigned g_epoch;
__device__ unsigned g_scnt;              // logits-partials arrival counter
__device__ volatile unsigned g_sdone;    // sampler progress: == t+1 after step t sampled

// ---------------- threefry2x32 (JAX partitionable) ----------------
__device__ __forceinline__ void tf2x32(uint32_t k0, uint32_t k1, uint32_t& x0, uint32_t& x1) {
    uint32_t ks2 = k0 ^ k1 ^ 0x1BD11BDAu;
    x0 += k0; x1 += k1;
#define TF_RND(r) { x0 += x1; x1 = (x1 << (r)) | (x1 >> (32 - (r))); x1 ^= x0; }
    TF_RND(13) TF_RND(15) TF_RND(26) TF_RND(6)   x0 += k1;  x1 += ks2 + 1u;
    TF_RND(17) TF_RND(29) TF_RND(16) TF_RND(24)  x0 += ks2; x1 += k0 + 2u;
    TF_RND(13) TF_RND(15) TF_RND(26) TF_RND(6)   x0 += k0;  x1 += k1 + 3u;
    TF_RND(17) TF_RND(29) TF_RND(16) TF_RND(24)  x0 += k1;  x1 += ks2 + 4u;
    TF_RND(13) TF_RND(15) TF_RND(26) TF_RND(6)   x0 += ks2; x1 += k0 + 5u;
#undef TF_RND
}

__global__ void k_keys() {
    int t = threadIdx.x;
    uint32_t x0 = 0u, x1 = (uint32_t)t;
    tf2x32(0u, 42u, x0, x1);
    g_keys2[2 * t] = x0;
    g_keys2[2 * t + 1] = x1;
}

__global__ void k_gumbel() {
    int idx = blockIdx.x * blockDim.x + threadIdx.x;
    int t = idx >> 12;
    int i = idx & (OUT_SZ - 1);
    uint32_t x0 = 0u, x1 = (uint32_t)i;
    tf2x32(g_keys2[2 * t], g_keys2[2 * t + 1], x0, x1);
    uint32_t bits = x0 ^ x1;
    float f = __uint_as_float((bits >> 9) | 0x3f800000u) - 1.0f;
    const float TINY = 1.17549435e-38f;
    float u = fmaxf(f + TINY, TINY);
    g_gum[idx] = -logf(-logf(u));
}

__global__ void k_init(const float* __restrict__ h0in, const float* __restrict__ c0in) {
    int i = blockIdx.x * blockDim.x + threadIdx.x;
    if (i < H) {
        g_h0[0][i] = h0in[i];
        g_c0[i]    = c0in[i];
        g_h1[0][i] = h0in[H + i];
        g_c1[i]    = c0in[H + i];
    }
    if (i == 0) { g_prev = 1.0f; g_cnt = 0u; g_epoch = 0u; g_scnt = 0u; g_sdone = 0u; }
}

__global__ void k_convert(const float* __restrict__ Whh0, const float* __restrict__ Wih1,
                          const float* __restrict__ Whh1, const float* __restrict__ Wl,
                          const float* __restrict__ Wih0,
                          const float* __restrict__ bih1, const float* __restrict__ bhh1) {
    long i = (long)blockIdx.x * blockDim.x + threadIdx.x;
    const long N1 = (long)G4 * H;
    if (i < N1) {
        g_Whh0b[i] = __float2bfloat16(Whh0[i]);
        g_Wih1b[i] = __float2bfloat16(Wih1[i]);
        g_Whh1b[i] = __float2bfloat16(Whh1[i]);
    }
    if (i < (long)OUT_SZ * H) g_Wlb[i] = __float2bfloat16(Wl[i]);
    if (i < G4) {
        g_wcol0[i] = Wih0[i * (IN_SZ + 1)];
        g_bsum1[i] = bih1[i] + bhh1[i];
    }
}

__global__ void k_a0(const float* __restrict__ Wih0, const float* __restrict__ inp,
                     const float* __restrict__ bih0, const float* __restrict__ bhh0) {
    int idx = blockIdx.x * blockDim.x + threadIdx.x;
    int r = idx & (G4 - 1);
    int t = idx >> 13;
    float acc = bih0[r] + bhh0[r];
    const float* w = Wih0 + (size_t)r * (IN_SZ + 1) + 1;
    const float* x = inp + (size_t)t * IN_SZ;
#pragma unroll
    for (int k = 0; k < IN_SZ; k++) acc += w[k] * x[k];
    g_A0[t * G4 + r] = acc;
}

__device__ __forceinline__ float sigf(float x) { return 1.0f / (1.0f + expf(-x)); }
__device__ __forceinline__ float blo(uint32_t u) { return __uint_as_float(u << 16); }
__device__ __forceinline__ float bhi(uint32_t u) { return __uint_as_float(u & 0xffff0000u); }

__device__ __forceinline__ float bfdot8(uint4 w, float4 a, float4 b) {
    return blo(w.x) * a.x + bhi(w.x) * a.y
         + blo(w.y) * a.z + bhi(w.y) * a.w
         + blo(w.z) * b.x + bhi(w.z) * b.y
         + blo(w.w) * b.z + bhi(w.w) * b.w;
}

__device__ __forceinline__ float warp_sum(float v) {
#pragma unroll
    for (int o = 16; o; o >>= 1) v += __shfl_down_sync(0xffffffffu, v, o);
    return v;
}

// grid-wide barrier among the 128 worker blocks
__device__ __forceinline__ void gbar(unsigned target) {
    __syncthreads();
    if (threadIdx.x == 0) {
        unsigned a = atomicAdd(&g_cnt, 1u);
        if (a == NBLK_W - 1u) {
            g_cnt = 0u;
            __threadfence();
            g_epoch = target;
        } else {
            while (g_epoch < target) {}
        }
    }
    __syncthreads();
}

__global__ void __launch_bounds__(NTHR, 1) k_persist(const float* __restrict__ bl,
                                                     float* __restrict__ out) {
    extern __shared__ char smem[];
    const int tid  = threadIdx.x;
    const int warp = tid >> 5, lane = tid & 31;
    const int b = blockIdx.x;

    __shared__ float sg[64], sg2[64];
    __shared__ float sA0[64];
    __shared__ float sgum[32], sbl[32], slog[32], sper[32];
    __shared__ float rm[4], rlm[4], rs[4], s_Mv;
    __shared__ int rix[4], s_Iv;

    // ================= dedicated sampler block =================
    if (b == NBLK_W) {
        for (int t = 0; t < T_STEPS; t++) {
            if (tid == 0) {
                while (*(volatile unsigned*)&g_scnt < (unsigned)NBLK_W) {}
            }
            __syncthreads();
            // combine 128 partials: argmax(pert), max(logit)
            float pm = -CUDART_INF_F; int pi = 0; float lm = -CUDART_INF_F;
            if (tid < NBLK_W) {
                pm = __ldcg(&g_bm[tid]);
                pi = __ldcg(&g_bi[tid]);
                lm = __ldcg(&g_blm[tid]);
            }
#pragma unroll
            for (int o = 16; o; o >>= 1) {
                float om = __shfl_down_sync(0xffffffffu, pm, o);
                int   oi = __shfl_down_sync(0xffffffffu, pi, o);
                float ol = __shfl_down_sync(0xffffffffu, lm, o);
                if (om > pm || (om == pm && oi < pi)) { pm = om; pi = oi; }
                lm = fmaxf(lm, ol);
            }
            if (lane == 0 && warp < 4) { rm[warp] = pm; rix[warp] = pi; rlm[warp] = lm; }
            __syncthreads();
            if (tid == 0) {
                pm = rm[0]; pi = rix[0]; lm = rlm[0];
#pragma unroll
                for (int w = 1; w < 4; w++) {
                    if (rm[w] > pm || (rm[w] == pm && rix[w] < pi)) { pm = rm[w]; pi = rix[w]; }
                    lm = fmaxf(lm, rlm[w]);
                }
                s_Mv = lm; s_Iv = pi;
            }
            __syncthreads();
            float M = s_Mv;
            float contrib = 0.f;
            if (tid < NBLK_W)
                contrib = __ldcg(&g_bs[tid]) * expf(__ldcg(&g_blm[tid]) - M);
            contrib = warp_sum(contrib);
            if (lane == 0 && warp < 4) rs[warp] = contrib;
            __syncthreads();
            if (tid == 0) {
                float S = rs[0] + rs[1] + rs[2] + rs[3];
                out[t] = (float)s_Iv;
                __stcg(&g_prev, (float)s_Iv);
                __stcg(&g_M, M);
                __stcg(&g_S, S);
                g_scnt = 0u;
                __threadfence();
                g_sdone = (unsigned)(t + 1);
            }
            __syncthreads();
        }
        return;
    }

    // ================= worker blocks =================
    __nv_bfloat16* ws = (__nv_bfloat16*)smem;            // 48 Whh0 rows x 2048 bf16
    float* hs = (float*)(smem + SMEM_W_BYTES);           // 2 x 2048 fp32 stage
    const int c0 = b * COLS_PER_BLK;

    // per-thread persistent state (tid<16): cell c values + per-gate constants
    float c0r = 0.f, c1r = 0.f, w0r[4], bs1r[4];
    if (tid < COLS_PER_BLK) {
        int col = c0 + tid;
        c0r = g_c0[col];
        c1r = g_c1[col];
#pragma unroll
        for (int g = 0; g < 4; g++) {
            w0r[g]  = g_wcol0[g * H + col];
            bs1r[g] = g_bsum1[g * H + col];
        }
    }
    if (tid < 32) sbl[tid] = bl[b * 32 + tid];

    // load Whh0 slice into smem (rows: slot = j*4+g, j<SMEM_COLS)
    for (int slot = warp; slot < SMEM_COLS * 4; slot += 16) {
        int j = slot >> 2, g = slot & 3;
        const uint4* src = (const uint4*)(g_Whh0b + ((size_t)(g * H + c0 + j)) * H);
        uint4* dst = (uint4*)(ws + (size_t)slot * H);
        for (int i = lane; i < H / 8; i += 32) dst[i] = src[i];
    }

    for (int t = 0; t < T_STEPS; t++) {
        int ph = t & 1;

        // ======== WINDOW A: everything not needing sample(t-1) ========
        __syncthreads();
        {   // stage h0_old -> hs[0..2047], h1_old -> hs[2048..4095]
            const float4* sa = (const float4*)g_h0[ph];
            const float4* sb = (const float4*)g_h1[ph];
            float4* dst = (float4*)hs;
            for (int i = tid; i < H / 4; i += NTHR) dst[i] = __ldcg(sa + i);
            for (int i = tid; i < H / 4; i += NTHR) dst[H / 4 + i] = __ldcg(sb + i);
        }
        if (tid < 64) sA0[tid] = g_A0[t * G4 + (tid & 3) * H + c0 + (tid >> 2)];
        else if (tid < 96) sgum[tid - 64] = g_gum[t * OUT_SZ + b * 32 + (tid - 64)];
        __syncthreads();

        // layer0 dots (Whh0 @ h0_old) -> sg
#pragma unroll
        for (int p = 0; p < 4; p++) {
            int ri = p * 16 + warp;
            int j = ri >> 2, g = ri & 3;
            const uint4* W = (j < SMEM_COLS)
                ? (const uint4*)(ws + (size_t)ri * H)
                : (const uint4*)(g_Whh0b + ((size_t)(g * H + c0 + j)) * H);
            const float4* hv = (const float4*)hs;
            float acc = 0.f;
#pragma unroll
            for (int i = 0; i < 8; i++) {
                uint4 w = W[i * 32 + lane];
                acc += bfdot8(w, hv[(i * 32 + lane) * 2], hv[(i * 32 + lane) * 2 + 1]);
            }
            acc = warp_sum(acc);
            if (lane == 0) sg[ri] = acc;
        }
        // Whh1 @ h1_old dots -> sg2 (half of layer1 hoisted off critical path)
#pragma unroll
        for (int p = 0; p < 4; p++) {
            int ri = p * 16 + warp;
            int j = ri >> 2, g = ri & 3;
            const uint4* W = (const uint4*)(g_Whh1b + ((size_t)(g * H + c0 + j)) * H);
            const float4* hv = (const float4*)hs + (H / 4);   // h1_old region
            float acc = 0.f;
#pragma unroll
            for (int i = 0; i < 8; i++) {
                uint4 w = W[i * 32 + lane];
                acc += bfdot8(w, hv[(i * 32 + lane) * 2], hv[(i * 32 + lane) * 2 + 1]);
            }
            acc = warp_sum(acc);
            if (lane == 0) sg2[ri] = acc;
        }

        // ======== wait for sampler(t-1) ========
        if (tid == 0) { while (g_sdone < (unsigned)t) {} }
        __syncthreads();

        // probs(t-1) write (warps 1) overlapped with cell0 (warp 0 threads 0..15)
        if (t > 0 && tid >= 32 && tid < 64) {
            float M = __ldcg(&g_M), S = __ldcg(&g_S);
            out[T_STEPS + (size_t)(t - 1) * OUT_SZ + b * 32 + (tid - 32)] =
                expf(slog[tid - 32] - M) / S;
        }
        if (tid < COLS_PER_BLK) {
            int col = c0 + tid;
            float prev = __ldcg(&g_prev);
            float gg[4];
#pragma unroll
            for (int g = 0; g < 4; g++)
                gg[g] = sg[tid * 4 + g] + sA0[tid * 4 + g] + w0r[g] * prev;
            c0r = sigf(gg[1]) * c0r + sigf(gg[0]) * tanhf(gg[2]);
            __stcg(&g_h0[ph ^ 1][col], sigf(gg[3]) * tanhf(c0r));
            __threadfence();
        }
        gbar((unsigned)(2 * t + 1));

        // ======== layer1 critical half: Wih1 @ h0_new ========
        {
            const float4* src = (const float4*)g_h0[ph ^ 1];
            float4* dst = (float4*)hs;
            for (int i = tid; i < H / 4; i += NTHR) dst[i] = __ldcg(src + i);
        }
        __syncthreads();
#pragma unroll
        for (int p = 0; p < 4; p++) {
            int ri = p * 16 + warp;
            int j = ri >> 2, g = ri & 3;
            const uint4* W = (const uint4*)(g_Wih1b + ((size_t)(g * H + c0 + j)) * H);
            const float4* hv = (const float4*)hs;
            float acc = 0.f;
#pragma unroll
            for (int i = 0; i < 8; i++) {
                uint4 w = W[i * 32 + lane];
                acc += bfdot8(w, hv[(i * 32 + lane) * 2], hv[(i * 32 + lane) * 2 + 1]);
            }
            acc = warp_sum(acc);
            if (lane == 0) sg[ri] = acc + sg2[ri];
        }
        __syncthreads();
        if (tid < COLS_PER_BLK) {
            int col = c0 + tid;
            float gg[4];
#pragma unroll
            for (int g = 0; g < 4; g++) gg[g] = sg[tid * 4 + g] + bs1r[g];
            c1r = sigf(gg[1]) * c1r + sigf(gg[0]) * tanhf(gg[2]);
            __stcg(&g_h1[ph ^ 1][col], sigf(gg[3]) * tanhf(c1r));
            __threadfence();
        }
        gbar((unsigned)(2 * t + 2));

        // ======== logits for this block's 32 rows ========
        {
            const float4* src = (const float4*)g_h1[ph ^ 1];
            float4* dst = (float4*)hs;
            for (int i = tid; i < H / 4; i += NTHR) dst[i] = __ldcg(src + i);
        }
        __syncthreads();
#pragma unroll
        for (int p = 0; p < 2; p++) {
            int s = p * 16 + warp;
            int r = b * 32 + s;
            const uint4* W = (const uint4*)(g_Wlb + (size_t)r * H);
            const float4* hv = (const float4*)hs;
            float acc = 0.f;
#pragma unroll
            for (int i = 0; i < 8; i++) {
                uint4 w = W[i * 32 + lane];
                acc += bfdot8(w, hv[(i * 32 + lane) * 2], hv[(i * 32 + lane) * 2 + 1]);
            }
            acc = warp_sum(acc);
            if (lane == 0) {
                float lg = acc + sbl[s];
                slog[s] = lg;
                sper[s] = lg + sgum[s];
            }
        }
        __syncthreads();

        // block-local partials + arrival (warp 0 only)
        if (warp == 0) {
            float lg = slog[lane], pp = sper[lane];
            int idx = b * 32 + lane;
            float bm = pp; int bi = idx; float lm = lg;
#pragma unroll
            for (int o = 16; o; o >>= 1) {
                float om = __shfl_down_sync(0xffffffffu, bm, o);
                int   oi = __shfl_down_sync(0xffffffffu, bi, o);
                float ol = __shfl_down_sync(0xffffffffu, lm, o);
                if (om > bm || (om == bm && oi < bi)) { bm = om; bi = oi; }
                lm = fmaxf(lm, ol);
            }
            lm = __shfl_sync(0xffffffffu, lm, 0);
            float e = expf(lg - lm);
            e = warp_sum(e);
            if (lane == 0) {
                __stcg(&g_bm[b], bm);
                __stcg(&g_bi[b], bi);
                __stcg(&g_blm[b], lm);
                __stcg(&g_bs[b], e);
                __threadfence();
                atomicAdd(&g_scnt, 1u);
            }
        }
        // no block-wide wait: next iteration's Window A overlaps sampler combine
    }

    // final: wait for last sampler, write probs(T-1)
    if (tid == 0) { while (g_sdone < (unsigned)T_STEPS) {} }
    __syncthreads();
    if (tid < 32) {
        float M = __ldcg(&g_M), S = __ldcg(&g_S);
        out[T_STEPS + (size_t)(T_STEPS - 1) * OUT_SZ + b * 32 + tid] =
            expf(slog[tid] - M) / S;
    }
}

// ---------------- host launcher ----------------
extern "C" void kernel_launch(void* const* d_in, const int* in_sizes, int n_in,
                              void* d_out, int out_size) {
    const float* input = (const float*)d_in[0];
    const float* h0    = (const float*)d_in[1];
    const float* c0    = (const float*)d_in[2];
    const float* Wih0  = (const float*)d_in[3];
    const float* Whh0  = (const float*)d_in[4];
    const float* bih0  = (const float*)d_in[5];
    const float* bhh0  = (const float*)d_in[6];
    const float* Wih1  = (const float*)d_in[7];
    const float* Whh1  = (const float*)d_in[8];
    const float* bih1  = (const float*)d_in[9];
    const float* bhh1  = (const float*)d_in[10];
    const float* Wl    = (const float*)d_in[11];
    const float* bl    = (const float*)d_in[12];
    float* out = (float*)d_out;

    cudaFuncSetAttribute(k_persist, cudaFuncAttributeMaxDynamicSharedMemorySize, SMEM_BYTES);

    // Precompute (parallel, off the sequential critical path)
    k_convert<<<(G4 * H + 255) / 256, 256>>>(Whh0, Wih1, Whh1, Wl, Wih0, bih1, bhh1);
    k_keys<<<1, 128>>>();
    k_gumbel<<<(T_STEPS * OUT_SZ) / 256, 256>>>();
    k_init<<<(H + 255) / 256, 256>>>(h0, c0);
    k_a0<<<(T_STEPS * G4) / 256, 256>>>(Wih0, input, bih0, bhh0);

    // Single persistent kernel (128 workers + 1 sampler block)
    k_persist<<<GRID, NTHR, SMEM_BYTES>>>(bl, out);
}